// round 3
// baseline (speedup 1.0000x reference)
#include <cuda_runtime.h>
#include <math.h>

// CRF loss: out[b] = logZ(b) - label_score(b).  B=512, S=512, L=128.
//
// Scaled linear-space forward recursion, one block of 128 threads per batch.
// Thread j owns column j of E=exp(trans) packed into 64 f32x2 registers.
// Shared holds unnormalized U_j = exp(alpha_j - offset); per step:
//   s_j = sum_i U_i E_ij   (packed fma.rn.f32x2)
//   U'_j = s_j * r * exp(x_tj),  r = rcp(U_0)  (same r folded into offset)
// exp/log/LDG are all OFF the inter-thread critical path; U double-buffered
// so only ONE __syncthreads per step.

#define LDIM 128

__device__ __forceinline__ unsigned long long pack_f32x2(float lo, float hi) {
    unsigned long long r;
    asm("mov.b64 %0, {%1, %2};" : "=l"(r) : "f"(lo), "f"(hi));
    return r;
}
__device__ __forceinline__ void unpack_f32x2(unsigned long long v, float& lo, float& hi) {
    asm("mov.b64 {%0, %1}, %2;" : "=f"(lo), "=f"(hi) : "l"(v));
}
__device__ __forceinline__ unsigned long long fma_f32x2(unsigned long long a,
                                                        unsigned long long b,
                                                        unsigned long long c) {
    unsigned long long d;
    asm("fma.rn.f32x2 %0, %1, %2, %3;" : "=l"(d) : "l"(a), "l"(b), "l"(c));
    return d;
}
__device__ __forceinline__ float rcp_approx(float x) {
    float r;
    asm("rcp.approx.ftz.f32 %0, %1;" : "=f"(r) : "f"(x));
    return r;
}

__global__ __launch_bounds__(128, 3)
void crf_forward_kernel(const float* __restrict__ input,
                        const int*   __restrict__ label,
                        const int*   __restrict__ length,
                        const float* __restrict__ trans,
                        float* __restrict__ out,
                        int S)
{
    __shared__ __align__(16) float u_sh[2][LDIM];
    __shared__ float wred[4];
    __shared__ float s_x00;
    __shared__ float s_labelscore;

    const int tid = threadIdx.x;     // == state j
    const int j   = tid;
    const int b   = blockIdx.x;

    int len = length[b];
    len = len < 1 ? 1 : (len > S ? S : len);

    const float* xb   = input + (size_t)b * S * LDIM;
    const int*   labb = label + (size_t)b * S;

    // ---------------- label score (point + transition) ----------------
    float ls = 0.f;
    for (int t = tid; t < len; t += LDIM) {
        int lab = labb[t];
        ls += xb[(size_t)t * LDIM + lab];
        if (t + 1 < len) ls += trans[lab * LDIM + labb[t + 1]];
    }
    #pragma unroll
    for (int o = 16; o > 0; o >>= 1)
        ls += __shfl_xor_sync(0xffffffffu, ls, o);
    if ((tid & 31) == 0) wred[tid >> 5] = ls;
    __syncthreads();
    if (tid == 0)
        s_labelscore = (wred[0] + wred[1]) + (wred[2] + wred[3]);

    // ------------- E = exp(trans[:, j]) packed into 64 f32x2 regs -------
    unsigned long long E2[64];
    #pragma unroll
    for (int k = 0; k < 64; k++) {
        float lo = __expf(trans[(2 * k)     * LDIM + j]);
        float hi = __expf(trans[(2 * k + 1) * LDIM + j]);
        E2[k] = pack_f32x2(lo, hi);
    }

    // ---------------- init: U_0j = exp(x_0j - x_00), offset = x_00 ------
    float x0 = xb[j];
    if (j == 0) s_x00 = x0;
    __syncthreads();
    const float x00 = s_x00;
    float Ucur = __expf(x0 - x00);
    u_sh[0][j] = Ucur;

    // prefetch x two steps ahead
    int i1 = 1 < len ? 1 : 0;
    int i2 = 2 < len ? 2 : (len - 1);
    float xA = xb[(size_t)i1 * LDIM + j];   // for t = 1
    float xB = xb[(size_t)i2 * LDIM + j];   // for t = 2

    float acc_logr = 0.f;                   // thread 0 only
    __syncthreads();

    // ---------------- forward recursion: t = 1 .. len-1 ----------------
    int cur = 0;
    for (int t = 1; t < len; t++) {
        const int nxt = cur ^ 1;
        const float u0 = u_sh[cur][0];
        const float r  = rcp_approx(u0);          // off the FFMA chain
        const float ex = __expf(xA);               // off the FFMA chain

        // rotate prefetch pipeline (x for t+2)
        xA = xB;
        int tp = t + 2;
        if (tp > len - 1) tp = len - 1;
        xB = xb[(size_t)tp * LDIM + j];

        // s_j = sum_i U_i * E[i][j], packed f32x2, 4 accumulators
        unsigned long long acc0 = 0ull, acc1 = 0ull, acc2 = 0ull, acc3 = 0ull;
        const ulonglong2* u2 = (const ulonglong2*)u_sh[cur];
        #pragma unroll
        for (int k = 0; k < 64; k += 4) {
            ulonglong2 ua = u2[k >> 1];
            ulonglong2 ub = u2[(k >> 1) + 1];
            acc0 = fma_f32x2(ua.x, E2[k + 0], acc0);
            acc1 = fma_f32x2(ua.y, E2[k + 1], acc1);
            acc2 = fma_f32x2(ub.x, E2[k + 2], acc2);
            acc3 = fma_f32x2(ub.y, E2[k + 3], acc3);
        }
        float a0, a1, b0, b1, c0, c1, d0, d1;
        unpack_f32x2(acc0, a0, a1);
        unpack_f32x2(acc1, b0, b1);
        unpack_f32x2(acc2, c0, c1);
        unpack_f32x2(acc3, d0, d1);
        float s = ((a0 + a1) + (b0 + b1)) + ((c0 + c1) + (d0 + d1));

        Ucur = s * (r * ex);
        u_sh[nxt][j] = Ucur;
        if (j == 0) acc_logr += __logf(r);         // offset -= log r, off-path
        cur = nxt;
        __syncthreads();
    }

    // ---------------- z = x00 - acc_logr + log(sum_j U);  out = z - ls --
    float es = Ucur;
    #pragma unroll
    for (int o = 16; o > 0; o >>= 1)
        es += __shfl_xor_sync(0xffffffffu, es, o);
    if ((tid & 31) == 0) wred[tid >> 5] = es;
    __syncthreads();
    if (tid == 0) {
        float ssum = (wred[0] + wred[1]) + (wred[2] + wred[3]);
        float z = x00 - acc_logr + logf(ssum);
        out[b] = z - s_labelscore;
    }
}

extern "C" void kernel_launch(void* const* d_in, const int* in_sizes, int n_in,
                              void* d_out, int out_size)
{
    const float* input  = (const float*)d_in[0];   // (B, S, L) f32
    const int*   label  = (const int*)  d_in[1];   // (B, S) i32
    const int*   length = (const int*)  d_in[2];   // (B,) i32
    const float* trans  = (const float*)d_in[3];   // (L, L) f32
    float* out = (float*)d_out;                    // (B, 1) f32

    const int B = in_sizes[2];
    const int S = in_sizes[1] / B;

    crf_forward_kernel<<<B, 128>>>(input, label, length, trans, out, S);
}